// round 4
// baseline (speedup 1.0000x reference)
#include <cuda_runtime.h>

#define L      8192
#define KK     31
#define HALF   15
#define NT     512
#define CP     8                            // output PAIRS per thread (8 in each half-row)
#define WP     (CP + KK - 1)                // 38 sliding-window pairs
#define HALO   16
#define USEG   (L + 2*HALO)                 // 8224 logical padded length
#define PHYS   (USEG + (USEG >> 3) + 8)     // stride-9 padding: conflict-free for stride-8 lanes
#define XN     (L/2)                        // 4096 packed x pairs
#define XPHYS  (XN + (XN >> 3) + 8)
#define EPS    1e-6f

// physical index in padded SMEM row: logical i in [-HALO, L+HALO)
__device__ __forceinline__ int ph(int i) {
    int u = i + HALO;
    return u + (u >> 3);
}
__device__ __forceinline__ int xph(int i) { return i + (i >> 3); }

__device__ __forceinline__ unsigned long long pk2(float lo, float hi) {
    unsigned long long r;
    asm("mov.b64 %0, {%1, %2};" : "=l"(r) : "f"(lo), "f"(hi));
    return r;
}
__device__ __forceinline__ void upk2(unsigned long long v, float &lo, float &hi) {
    asm("mov.b64 {%0, %1}, %2;" : "=f"(lo), "=f"(hi) : "l"(v));
}
// d = a*b + d on packed f32x2 (sm_100+; PTX-only, ptxas never auto-fuses)
__device__ __forceinline__ void fma2(unsigned long long &d, unsigned long long a, unsigned long long b) {
    asm("fma.rn.f32x2 %0, %1, %2, %0;" : "+l"(d) : "l"(a), "l"(b));
}

// 31-tap conv producing CP packed (halfA, halfB) output pairs; acc pre-seeded with EPS.
__device__ __forceinline__ void conv_pairs(const float* __restrict__ src,
                                           const float* __restrict__ taps,
                                           int bA, int bB,
                                           unsigned long long acc[CP]) {
    unsigned long long r[WP];
    #pragma unroll
    for (int k = 0; k < WP; ++k)
        r[k] = pk2(src[ph(bA - HALF + k)], src[ph(bB - HALF + k)]);
    #pragma unroll
    for (int p = 0; p < CP; ++p) acc[p] = pk2(EPS, EPS);   // fold "+EPS" into init
    #pragma unroll
    for (int j = 0; j < KK; ++j) {
        const float w = taps[j];                            // LDS broadcast
        const unsigned long long wp = pk2(w, w);
        #pragma unroll
        for (int p = 0; p < CP; ++p)
            fma2(acc[p], r[p + j], wp);                     // window shifts whole pairs
    }
}

__global__ void __launch_bounds__(NT, 1)
drl_kernel(const float* __restrict__ m,
           const float* __restrict__ psf,
           const float* __restrict__ alpha,
           float* __restrict__ out,
           int nlayers) {
    extern __shared__ float smbuf[];
    float* S = smbuf;                                        // estimate, padded + halo
    float* T = smbuf + PHYS;                                 // ratio scratch, padded + halo
    unsigned long long* X = (unsigned long long*)(smbuf + 2 * PHYS); // pre-paired x row
    __shared__ float Wf[KK], Wr[KK];

    const int tid = threadIdx.x;
    const int row = blockIdx.x;

    if (tid < KK) {
        Wf[tid] = psf[tid];
        Wr[tid] = psf[KK - 1 - tid];
    }

    // init: S = 0.5 inside, 0 in halos; T halos = 0 (stay 0 forever)
    for (int u = tid; u < USEG; u += NT) {
        int p = u + (u >> 3);
        bool inside = (u >= HALO) && (u < HALO + L);
        S[p] = inside ? 0.5f : 0.0f;
        T[p] = 0.0f;
    }

    const int bA = tid * CP;
    const int bB = bA + XN;

    // x row: one coalesced HBM read, stored pre-paired (halfA, halfB) as u64 in SMEM
    {
        const float4* ma = (const float4*)(m + (size_t)row * L + bA);
        const float4* mb = (const float4*)(m + (size_t)row * L + bB);
        float4 a0 = ma[0], a1 = ma[1];
        float4 b0 = mb[0], b1 = mb[1];
        X[xph(bA + 0)] = pk2(a0.x, b0.x);
        X[xph(bA + 1)] = pk2(a0.y, b0.y);
        X[xph(bA + 2)] = pk2(a0.z, b0.z);
        X[xph(bA + 3)] = pk2(a0.w, b0.w);
        X[xph(bA + 4)] = pk2(a1.x, b1.x);
        X[xph(bA + 5)] = pk2(a1.y, b1.y);
        X[xph(bA + 6)] = pk2(a1.z, b1.z);
        X[xph(bA + 7)] = pk2(a1.w, b1.w);
    }
    __syncthreads();

    for (int layer = 0; layer < nlayers; ++layer) {
        const float a = alpha[layer];

        // ---- pass 1: s_conv = conv(S,w)+EPS ; ratio = x / s_conv -> T ----
        {
            unsigned long long acc[CP];
            conv_pairs(S, Wf, bA, bB, acc);
            #pragma unroll
            for (int p = 0; p < CP; ++p) {
                float sa, sb, xa, xb;
                upk2(acc[p], sa, sb);
                upk2(X[xph(bA + p)], xa, xb);
                T[ph(bA + p)] = __fdividef(xa, sa);
                T[ph(bB + p)] = __fdividef(xb, sb);
            }
        }
        __syncthreads();

        // ---- pass 2: corr = max(conv(T,wflip)+EPS, EPS); S = max(S*corr^a, EPS) ----
        {
            unsigned long long acc[CP];
            conv_pairs(T, Wr, bA, bB, acc);
            #pragma unroll
            for (int p = 0; p < CP; ++p) {
                float ca, cb;
                upk2(acc[p], ca, cb);
                ca = fmaxf(ca, EPS);
                cb = fmaxf(cb, EPS);
                if (a != 1.0f) {                 // warp-uniform; skipped for alpha==1
                    ca = __powf(ca, a);
                    cb = __powf(cb, a);
                }
                const int pa = ph(bA + p), pb = ph(bB + p);
                S[pa] = fmaxf(S[pa] * ca, EPS);
                S[pb] = fmaxf(S[pb] * cb, EPS);
            }
        }
        __syncthreads();
    }

    // coalesced output store
    {
        float* orow = out + (size_t)row * L;
        float4 oa0, oa1, ob0, ob1;
        oa0.x = S[ph(bA + 0)]; oa0.y = S[ph(bA + 1)]; oa0.z = S[ph(bA + 2)]; oa0.w = S[ph(bA + 3)];
        oa1.x = S[ph(bA + 4)]; oa1.y = S[ph(bA + 5)]; oa1.z = S[ph(bA + 6)]; oa1.w = S[ph(bA + 7)];
        ob0.x = S[ph(bB + 0)]; ob0.y = S[ph(bB + 1)]; ob0.z = S[ph(bB + 2)]; ob0.w = S[ph(bB + 3)];
        ob1.x = S[ph(bB + 4)]; ob1.y = S[ph(bB + 5)]; ob1.z = S[ph(bB + 6)]; ob1.w = S[ph(bB + 7)];
        ((float4*)(orow + bA))[0] = oa0;
        ((float4*)(orow + bA))[1] = oa1;
        ((float4*)(orow + bB))[0] = ob0;
        ((float4*)(orow + bB))[1] = ob1;
    }
}

extern "C" void kernel_launch(void* const* d_in, const int* in_sizes, int n_in,
                              void* d_out, int out_size) {
    const float* m     = (const float*)d_in[0];
    const float* psf   = (const float*)d_in[1];
    const float* alpha = (const float*)d_in[2];
    float* out = (float*)d_out;

    const int nlayers = in_sizes[2];
    const int B = in_sizes[0] / L;
    const int smem_bytes = (2 * PHYS) * (int)sizeof(float) + XPHYS * (int)sizeof(unsigned long long);

    cudaFuncSetAttribute(drl_kernel, cudaFuncAttributeMaxDynamicSharedMemorySize, smem_bytes);
    drl_kernel<<<B, NT, smem_bytes>>>(m, psf, alpha, out, nlayers);
}

// round 5
// speedup vs baseline: 1.2143x; 1.2143x over previous
#include <cuda_runtime.h>

#define L      8192
#define NPAIR  (L/2)          // 4096 packed (lo=i, hi=i+4096) pairs
#define KK     31
#define HALF   15
#define NT     256
#define CP     16             // output pairs per thread
#define WP     (CP + KK - 1)  // 46 window pairs
#define ULEN   (NPAIR + 2*HALF)             // 4126 logical pairs incl halos
#define PHYS64 (ULEN + (ULEN >> 4) + 2)     // padded u64 length (4385)
#define EPS    1e-6f

typedef unsigned long long u64;

// physical index for pair arrays; logical pair i in [-15, NPAIR+15)
__device__ __forceinline__ int p64(int i) {
    int u = i + HALF;
    return u + (u >> 4);      // stride-17 physical: conflict-free for stride-16 lanes
}

__device__ __forceinline__ u64 pk2(float lo, float hi) {
    u64 r;
    asm("mov.b64 %0, {%1, %2};" : "=l"(r) : "f"(lo), "f"(hi));
    return r;
}
__device__ __forceinline__ void upk2(u64 v, float &lo, float &hi) {
    asm("mov.b64 {%0, %1}, %2;" : "=f"(lo), "=f"(hi) : "l"(v));
}
// d = a*b + d on packed f32x2 (sm_100+; PTX-only)
__device__ __forceinline__ void fma2(u64 &d, u64 a, u64 b) {
    asm("fma.rn.f32x2 %0, %1, %2, %0;" : "+l"(d) : "l"(a), "l"(b));
}

#define EPS2 0x358637BD358637BDULL   // (1e-6f, 1e-6f) packed

// 31-tap conv over packed pairs, software-pipelined window (peak ~19 live u64)
__device__ __forceinline__ void conv_pairs(const u64* __restrict__ src,
                                           const u64* __restrict__ taps,
                                           int b, u64 acc[CP]) {
    u64 r[WP];
    #pragma unroll
    for (int k = 0; k < 18; ++k)
        r[k] = src[p64(b - HALF + k)];
    #pragma unroll
    for (int p = 0; p < CP; ++p) acc[p] = EPS2;     // "+EPS" folded into init
    #pragma unroll
    for (int j = 0; j < KK; ++j) {
        if (j + 18 < WP)                             // prefetch 3 taps ahead
            r[j + 18] = src[p64(b - HALF + j + 18)];
        const u64 w = taps[j];                       // LDS.64 broadcast, pre-packed (w,w)
        #pragma unroll
        for (int p = 0; p < CP; ++p)
            fma2(acc[p], r[p + j], w);
    }
}

__global__ void __launch_bounds__(NT, 2)
drl_kernel(const float* __restrict__ m,
           const float* __restrict__ psf,
           const float* __restrict__ alpha,
           float* __restrict__ out,
           int nlayers) {
    extern __shared__ u64 smbuf[];
    u64* S = smbuf;                 // estimate pairs, padded + halos
    u64* T = smbuf + PHYS64;        // ratio pairs, padded + halos
    __shared__ u64 Wf[KK], Wr[KK];

    const int tid = threadIdx.x;
    const int row = blockIdx.x;

    if (tid < KK) {
        float w = psf[tid];
        float v = psf[KK - 1 - tid];
        Wf[tid] = pk2(w, w);
        Wr[tid] = pk2(v, v);
    }

    // init S (incl. halo pairs): pair i = (s[i], s[i+4096]); s=0.5 inside row
    for (int u = tid; u < ULEN; u += NT) {
        int i = u - HALF;
        float lo = (i >= 0)     ? 0.5f : 0.0f;   // i <= 4110 < 8192 always in-row if >=0
        float hi = (i < NPAIR)  ? 0.5f : 0.0f;
        S[u + (u >> 4)] = pk2(lo, hi);
    }

    const int b = tid * CP;

    // x row pre-paired into 16 persistent registers (one coalesced HBM read)
    u64 xr[CP];
    {
        const float* mrow = m + (size_t)row * L;
        const float4* ma = (const float4*)(mrow + b);
        const float4* mb = (const float4*)(mrow + b + NPAIR);
        #pragma unroll
        for (int q = 0; q < 4; ++q) {
            float4 av = ma[q], bv = mb[q];
            xr[q * 4 + 0] = pk2(av.x, bv.x);
            xr[q * 4 + 1] = pk2(av.y, bv.y);
            xr[q * 4 + 2] = pk2(av.z, bv.z);
            xr[q * 4 + 3] = pk2(av.w, bv.w);
        }
    }
    __syncthreads();

    for (int layer = 0; layer < nlayers; ++layer) {
        const float a = alpha[layer];

        // ---- pass 1: ratio = x / (conv(S,w)+EPS) -> T (+ seam halos) ----
        {
            u64 acc[CP];
            conv_pairs(S, Wf, b, acc);
            #pragma unroll
            for (int p = 0; p < CP; ++p) {
                float sa, sb, xa, xb;
                upk2(acc[p], sa, sb);
                upk2(xr[p], xa, xb);
                T[p64(b + p)] = pk2(__fdividef(xa, sa), __fdividef(xb, sb));
            }
            // seam halos: right halo from thread 0's hi lanes, left from last thread's lo lanes
            if (tid == 0) {
                #pragma unroll
                for (int p = 0; p < HALF; ++p) {
                    float lo, hi; upk2(T[p64(p)], lo, hi);
                    T[p64(NPAIR + p)] = pk2(hi, 0.0f);
                }
            }
            if (tid == NT - 1) {
                #pragma unroll
                for (int p = 1; p <= HALF; ++p) {
                    float lo, hi; upk2(T[p64(b + p)], lo, hi);
                    T[p64(b + p - NPAIR)] = pk2(0.0f, lo);
                }
            }
        }
        __syncthreads();

        // ---- pass 2: corr = max(conv(T,wflip)+EPS, EPS); S = max(S*corr^a, EPS) ----
        {
            u64 acc[CP];
            conv_pairs(T, Wr, b, acc);
            #pragma unroll
            for (int p = 0; p < CP; ++p) {
                float ca, cb;
                upk2(acc[p], ca, cb);
                ca = fmaxf(ca, EPS);
                cb = fmaxf(cb, EPS);
                if (a != 1.0f) {               // warp-uniform; skipped for alpha==1
                    ca = __powf(ca, a);
                    cb = __powf(cb, a);
                }
                float so, sh;
                upk2(S[p64(b + p)], so, sh);
                so = fmaxf(so * ca, EPS);
                sh = fmaxf(sh * cb, EPS);
                S[p64(b + p)] = pk2(so, sh);
            }
            if (tid == 0) {
                #pragma unroll
                for (int p = 0; p < HALF; ++p) {
                    float lo, hi; upk2(S[p64(p)], lo, hi);
                    S[p64(NPAIR + p)] = pk2(hi, 0.0f);
                }
            }
            if (tid == NT - 1) {
                #pragma unroll
                for (int p = 1; p <= HALF; ++p) {
                    float lo, hi; upk2(S[p64(b + p)], lo, hi);
                    S[p64(b + p - NPAIR)] = pk2(0.0f, lo);
                }
            }
        }
        __syncthreads();
    }

    // coalesced output store: unpack pairs into the two half-row segments
    {
        float* orow = out + (size_t)row * L;
        #pragma unroll
        for (int q = 0; q < 4; ++q) {
            float4 va, vb;
            float lo, hi;
            upk2(S[p64(b + q * 4 + 0)], lo, hi); va.x = lo; vb.x = hi;
            upk2(S[p64(b + q * 4 + 1)], lo, hi); va.y = lo; vb.y = hi;
            upk2(S[p64(b + q * 4 + 2)], lo, hi); va.z = lo; vb.z = hi;
            upk2(S[p64(b + q * 4 + 3)], lo, hi); va.w = lo; vb.w = hi;
            ((float4*)(orow + b))[q] = va;
            ((float4*)(orow + b + NPAIR))[q] = vb;
        }
    }
}

extern "C" void kernel_launch(void* const* d_in, const int* in_sizes, int n_in,
                              void* d_out, int out_size) {
    const float* m     = (const float*)d_in[0];
    const float* psf   = (const float*)d_in[1];
    const float* alpha = (const float*)d_in[2];
    float* out = (float*)d_out;

    const int nlayers = in_sizes[2];
    const int B = in_sizes[0] / L;
    const int smem_bytes = 2 * PHYS64 * (int)sizeof(u64);

    cudaFuncSetAttribute(drl_kernel, cudaFuncAttributeMaxDynamicSharedMemorySize, smem_bytes);
    drl_kernel<<<B, NT, smem_bytes>>>(m, psf, alpha, out, nlayers);
}